// round 1
// baseline (speedup 1.0000x reference)
#include <cuda_runtime.h>
#include <cuda_bf16.h>

#define N_NODES 50000
#define N_EDGES 800000
#define F 128
#define CH 256
#define NCH ((N_NODES + CH - 1) / CH)   // 196

// ---- scratch (no allocation allowed -> __device__ globals) ----
__device__ int   g_deg_src[N_NODES];
__device__ int   g_deg_dst[N_NODES];
__device__ float g_out_norm[N_NODES];
__device__ float g_in_norm[N_NODES];
__device__ int   g_row_ptr[N_NODES + 1];
__device__ int   g_cursor[N_NODES];
__device__ int   g_col_idx[N_EDGES];
__device__ int   g_chunk_sum[NCH];
__device__ int   g_chunk_off[NCH];
__device__ float g_m[N_NODES * F];
__device__ float g_h[N_NODES * F];
__device__ float g_vec[F];

// ---------------- setup kernels ----------------
__global__ void k_init() {
    int i = blockIdx.x * blockDim.x + threadIdx.x;
    if (i < N_NODES) { g_deg_src[i] = 0; g_deg_dst[i] = 0; }
    if (i < F) g_vec[i] = 0.f;
}

__global__ void k_count(const int* __restrict__ src, const int* __restrict__ dst) {
    int e = blockIdx.x * blockDim.x + threadIdx.x;
    if (e < N_EDGES) {
        atomicAdd(&g_deg_src[src[e]], 1);
        atomicAdd(&g_deg_dst[dst[e]], 1);
    }
}

// inclusive scan of deg_dst within 256-chunks; local result to row_ptr[i+1]
__global__ void k_scan1() {
    __shared__ int s[CH];
    int t = threadIdx.x;
    int i = blockIdx.x * CH + t;
    int v = (i < N_NODES) ? g_deg_dst[i] : 0;
    s[t] = v;
    __syncthreads();
    for (int off = 1; off < CH; off <<= 1) {
        int x = 0;
        if (t >= off) x = s[t - off];
        __syncthreads();
        if (t >= off) s[t] += x;
        __syncthreads();
    }
    if (i < N_NODES) g_row_ptr[i + 1] = s[t];
    if (t == CH - 1) g_chunk_sum[blockIdx.x] = s[t];
}

// exclusive scan of 196 chunk sums (single block)
__global__ void k_scan2() {
    __shared__ int s[CH];
    int t = threadIdx.x;
    int v = (t < NCH) ? g_chunk_sum[t] : 0;
    s[t] = v;
    __syncthreads();
    for (int off = 1; off < CH; off <<= 1) {
        int x = 0;
        if (t >= off) x = s[t - off];
        __syncthreads();
        if (t >= off) s[t] += x;
        __syncthreads();
    }
    if (t < NCH) g_chunk_off[t] = s[t] - v;
}

// finalize row_ptr, cursor, norms
__global__ void k_scan3() {
    int i = blockIdx.x * blockDim.x + threadIdx.x;
    if (i >= N_NODES) return;
    int rp = g_row_ptr[i + 1] + g_chunk_off[i / CH];
    g_row_ptr[i + 1] = rp;
    g_cursor[i] = rp - g_deg_dst[i];
    g_out_norm[i] = rsqrtf((float)max(g_deg_src[i], 1));
    g_in_norm[i]  = rsqrtf((float)max(g_deg_dst[i], 1));
    if (i == 0) g_row_ptr[0] = 0;
}

__global__ void k_fill(const int* __restrict__ src, const int* __restrict__ dst) {
    int e = blockIdx.x * blockDim.x + threadIdx.x;
    if (e < N_EDGES) {
        int d = dst[e];
        int p = atomicAdd(&g_cursor[d], 1);
        g_col_idx[p] = src[e];
    }
}

// ---------------- aggregation: one warp per dst node ----------------
__global__ void k_agg(const float* __restrict__ x, float* __restrict__ m) {
    int w = (blockIdx.x * blockDim.x + threadIdx.x) >> 5;
    int lane = threadIdx.x & 31;
    if (w >= N_NODES) return;
    int beg = g_row_ptr[w], end = g_row_ptr[w + 1];
    const float4* x4 = (const float4*)x;
    float4 a0 = {0.f, 0.f, 0.f, 0.f};
    float4 a1 = {0.f, 0.f, 0.f, 0.f};
    int e = beg;
    for (; e + 1 < end; e += 2) {
        int s0 = g_col_idx[e], s1 = g_col_idx[e + 1];
        float w0 = g_out_norm[s0], w1 = g_out_norm[s1];
        float4 v0 = x4[s0 * 32 + lane];
        float4 v1 = x4[s1 * 32 + lane];
        a0.x += w0 * v0.x; a0.y += w0 * v0.y; a0.z += w0 * v0.z; a0.w += w0 * v0.w;
        a1.x += w1 * v1.x; a1.y += w1 * v1.y; a1.z += w1 * v1.z; a1.w += w1 * v1.w;
    }
    if (e < end) {
        int s0 = g_col_idx[e];
        float w0 = g_out_norm[s0];
        float4 v0 = x4[s0 * 32 + lane];
        a0.x += w0 * v0.x; a0.y += w0 * v0.y; a0.z += w0 * v0.z; a0.w += w0 * v0.w;
    }
    float sc = g_in_norm[w];
    float4 r;
    r.x = (a0.x + a1.x) * sc;
    r.y = (a0.y + a1.y) * sc;
    r.z = (a0.z + a1.z) * sc;
    r.w = (a0.w + a1.w) * sc;
    ((float4*)m)[w * 32 + lane] = r;
}

// layer-3 aggregation folded into a single 128-vector:
// g_vec = (1/N) * sum_i in_norm[i] * sum_{e: dst=i} out_norm[src]*x[src]
__global__ void k_agg3(const float* __restrict__ x) {
    __shared__ float sacc[F];
    int t = threadIdx.x;
    if (t < F) sacc[t] = 0.f;
    __syncthreads();
    int w = (blockIdx.x * blockDim.x + t) >> 5;
    int lane = t & 31;
    if (w < N_NODES) {
        int beg = g_row_ptr[w], end = g_row_ptr[w + 1];
        const float4* x4 = (const float4*)x;
        float4 a0 = {0.f, 0.f, 0.f, 0.f};
        float4 a1 = {0.f, 0.f, 0.f, 0.f};
        int e = beg;
        for (; e + 1 < end; e += 2) {
            int s0 = g_col_idx[e], s1 = g_col_idx[e + 1];
            float w0 = g_out_norm[s0], w1 = g_out_norm[s1];
            float4 v0 = x4[s0 * 32 + lane];
            float4 v1 = x4[s1 * 32 + lane];
            a0.x += w0 * v0.x; a0.y += w0 * v0.y; a0.z += w0 * v0.z; a0.w += w0 * v0.w;
            a1.x += w1 * v1.x; a1.y += w1 * v1.y; a1.z += w1 * v1.z; a1.w += w1 * v1.w;
        }
        if (e < end) {
            int s0 = g_col_idx[e];
            float w0 = g_out_norm[s0];
            float4 v0 = x4[s0 * 32 + lane];
            a0.x += w0 * v0.x; a0.y += w0 * v0.y; a0.z += w0 * v0.z; a0.w += w0 * v0.w;
        }
        float sc = g_in_norm[w] * (1.0f / N_NODES);
        atomicAdd(&sacc[lane * 4 + 0], (a0.x + a1.x) * sc);
        atomicAdd(&sacc[lane * 4 + 1], (a0.y + a1.y) * sc);
        atomicAdd(&sacc[lane * 4 + 2], (a0.z + a1.z) * sc);
        atomicAdd(&sacc[lane * 4 + 3], (a0.w + a1.w) * sc);
    }
    __syncthreads();
    if (t < F) atomicAdd(&g_vec[t], sacc[t]);
}

// ---------------- GEMM + bias + relu: y = relu(x @ W + b) ----------------
// block = 256 threads, 32 rows per block. W (128x128 fp32 = 64KB) + 32x128 m
// tile (16KB) in dynamic smem. 4x4 register tile per thread -> FMA bound.
#define GR 32
__global__ void k_gemm_relu(const float* __restrict__ x, const float* __restrict__ W,
                            const float* __restrict__ b, float* __restrict__ y) {
    extern __shared__ float smem[];
    float* sW = smem;            // [128][128]
    float* sM = smem + F * F;    // [GR][128]
    int t = threadIdx.x;
    int row0 = blockIdx.x * GR;

    for (int idx = t * 4; idx < F * F; idx += 256 * 4)
        *(float4*)&sW[idx] = *(const float4*)&W[idx];
    for (int idx = t * 4; idx < GR * F; idx += 256 * 4) {
        int r = idx / F, c = idx % F;
        int grow = row0 + r;
        float4 v = {0.f, 0.f, 0.f, 0.f};
        if (grow < N_NODES) v = *(const float4*)&x[grow * F + c];
        *(float4*)&sM[idx] = v;
    }
    __syncthreads();

    int tx = t & 31;        // col group: cols 4*tx..4*tx+3
    int ty = t >> 5;        // row group: rows ty*4..ty*4+3 within tile
    float acc[4][4];
#pragma unroll
    for (int r = 0; r < 4; r++)
#pragma unroll
        for (int c = 0; c < 4; c++) acc[r][c] = 0.f;

#pragma unroll 4
    for (int k = 0; k < F; k++) {
        float4 w4 = *(float4*)&sW[k * F + tx * 4];
#pragma unroll
        for (int r = 0; r < 4; r++) {
            float mv = sM[(ty * 4 + r) * F + k];
            acc[r][0] += mv * w4.x;
            acc[r][1] += mv * w4.y;
            acc[r][2] += mv * w4.z;
            acc[r][3] += mv * w4.w;
        }
    }

    float4 b4 = *(const float4*)&b[tx * 4];
#pragma unroll
    for (int r = 0; r < 4; r++) {
        int grow = row0 + ty * 4 + r;
        if (grow < N_NODES) {
            float4 o;
            o.x = fmaxf(acc[r][0] + b4.x, 0.f);
            o.y = fmaxf(acc[r][1] + b4.y, 0.f);
            o.z = fmaxf(acc[r][2] + b4.z, 0.f);
            o.w = fmaxf(acc[r][3] + b4.w, 0.f);
            *(float4*)&y[grow * F + tx * 4] = o;
        }
    }
}

// final 128x128 matvec: out = g_vec @ W3 + b3
__global__ void k_final(const float* __restrict__ W3, const float* __restrict__ b3,
                        float* __restrict__ out) {
    __shared__ float sv[F];
    int j = threadIdx.x;   // 128 threads
    sv[j] = g_vec[j];
    __syncthreads();
    float acc = b3[j];
#pragma unroll 8
    for (int k = 0; k < F; k++) acc += sv[k] * W3[k * F + j];
    out[j] = acc;
}

extern "C" void kernel_launch(void* const* d_in, const int* in_sizes, int n_in,
                              void* d_out, int out_size) {
    const float* feat = (const float*)d_in[0];
    const float* W1   = (const float*)d_in[1];
    const float* b1   = (const float*)d_in[2];
    const float* W2   = (const float*)d_in[3];
    const float* b2   = (const float*)d_in[4];
    const float* W3   = (const float*)d_in[5];
    const float* b3   = (const float*)d_in[6];
    const int*   src  = (const int*)d_in[7];
    const int*   dst  = (const int*)d_in[8];
    float* out = (float*)d_out;

    cudaFuncSetAttribute(k_gemm_relu, cudaFuncAttributeMaxDynamicSharedMemorySize,
                         (F * F + GR * F) * sizeof(float));

    void *pm, *ph;
    cudaGetSymbolAddress(&pm, g_m);
    cudaGetSymbolAddress(&ph, g_h);
    float* m = (float*)pm;
    float* h = (float*)ph;

    int nb_nodes = (N_NODES + 255) / 256;
    int nb_edges = (N_EDGES + 255) / 256;
    int nb_agg   = (N_NODES * 32 + 255) / 256;   // one warp per node
    int nb_gemm  = (N_NODES + GR - 1) / GR;
    size_t smem_gemm = (size_t)(F * F + GR * F) * sizeof(float);

    // graph setup: degrees -> CSR by dst -> norms
    k_init<<<nb_nodes, 256>>>();
    k_count<<<nb_edges, 256>>>(src, dst);
    k_scan1<<<NCH, CH>>>();
    k_scan2<<<1, CH>>>();
    k_scan3<<<nb_nodes, 256>>>();
    k_fill<<<nb_edges, 256>>>(src, dst);

    // layer 1
    k_agg<<<nb_agg, 256>>>(feat, m);
    k_gemm_relu<<<nb_gemm, 256, smem_gemm>>>(m, W1, b1, h);
    // layer 2
    k_agg<<<nb_agg, 256>>>(h, m);
    k_gemm_relu<<<nb_gemm, 256, smem_gemm>>>(m, W2, b2, h);
    // layer 3 (GEMM folded into mean): vec = mean_n(m3); out = vec @ W3 + b3
    k_agg3<<<nb_agg, 256>>>(h);
    k_final<<<1, F>>>(W3, b3, out);
}

// round 2
// speedup vs baseline: 1.1427x; 1.1427x over previous
#include <cuda_runtime.h>
#include <cuda_bf16.h>

#define N_NODES 50000
#define N_EDGES 800000
#define F 128
#define CH 256
#define NCH ((N_NODES + CH - 1) / CH)   // 196
#define GR 64                            // rows per fused block

// ---- scratch (no allocation allowed -> __device__ globals) ----
__device__ int   g_deg_src[N_NODES];
__device__ int   g_deg_dst[N_NODES];
__device__ float g_out_norm[N_NODES];
__device__ float g_in_norm[N_NODES];
__device__ int   g_row_ptr[N_NODES + 1];
__device__ int   g_cursor[N_NODES];
__device__ int   g_col_idx[N_EDGES];
__device__ int   g_chunk_sum[NCH];
__device__ int   g_chunk_off[NCH];
__device__ float g_h1[N_NODES * F];
__device__ float g_h2[N_NODES * F];
__device__ float g_vec[F];

// ---------------- setup kernels ----------------
__global__ void k_init() {
    int i = blockIdx.x * blockDim.x + threadIdx.x;
    if (i < N_NODES) { g_deg_src[i] = 0; g_deg_dst[i] = 0; }
    if (i < F) g_vec[i] = 0.f;
}

__global__ void k_count(const int* __restrict__ src, const int* __restrict__ dst) {
    int e = blockIdx.x * blockDim.x + threadIdx.x;
    if (e < N_EDGES) {
        atomicAdd(&g_deg_src[src[e]], 1);
        atomicAdd(&g_deg_dst[dst[e]], 1);
    }
}

// inclusive scan of deg_dst within 256-chunks
__global__ void k_scan1() {
    __shared__ int s[CH];
    int t = threadIdx.x;
    int i = blockIdx.x * CH + t;
    int v = (i < N_NODES) ? g_deg_dst[i] : 0;
    s[t] = v;
    __syncthreads();
    for (int off = 1; off < CH; off <<= 1) {
        int x = 0;
        if (t >= off) x = s[t - off];
        __syncthreads();
        if (t >= off) s[t] += x;
        __syncthreads();
    }
    if (i < N_NODES) g_row_ptr[i + 1] = s[t];
    if (t == CH - 1) g_chunk_sum[blockIdx.x] = s[t];
}

// exclusive scan of chunk sums (single block)
__global__ void k_scan2() {
    __shared__ int s[CH];
    int t = threadIdx.x;
    int v = (t < NCH) ? g_chunk_sum[t] : 0;
    s[t] = v;
    __syncthreads();
    for (int off = 1; off < CH; off <<= 1) {
        int x = 0;
        if (t >= off) x = s[t - off];
        __syncthreads();
        if (t >= off) s[t] += x;
        __syncthreads();
    }
    if (t < NCH) g_chunk_off[t] = s[t] - v;
}

// finalize row_ptr, cursor, norms
__global__ void k_scan3() {
    int i = blockIdx.x * blockDim.x + threadIdx.x;
    if (i >= N_NODES) return;
    int rp = g_row_ptr[i + 1] + g_chunk_off[i / CH];
    g_row_ptr[i + 1] = rp;
    g_cursor[i] = rp - g_deg_dst[i];
    g_out_norm[i] = rsqrtf((float)max(g_deg_src[i], 1));
    g_in_norm[i]  = rsqrtf((float)max(g_deg_dst[i], 1));
    if (i == 0) g_row_ptr[0] = 0;
}

__global__ void k_fill(const int* __restrict__ src, const int* __restrict__ dst) {
    int e = blockIdx.x * blockDim.x + threadIdx.x;
    if (e < N_EDGES) {
        int d = dst[e];
        int p = atomicAdd(&g_cursor[d], 1);
        g_col_idx[p] = src[e];
    }
}

// ---------------- fused layer: agg (-> smem) + GEMM + bias + relu + out_norm prescale ----
// 512 threads, GR=64 rows per block. smem: W[128][128] (64KB) + sM[64][128] (32KB).
// SRC_NORM: layer-1 gather applies per-edge out_norm[src]; later layers read
// activations already prescaled by out_norm (done in this kernel's epilogue).
template<bool SRC_NORM>
__global__ void k_fused(const float* __restrict__ x, const float* __restrict__ W,
                        const float* __restrict__ b, float* __restrict__ y) {
    extern __shared__ float smem[];
    float* sW = smem;            // [128][128]
    float* sM = smem + F * F;    // [GR][128]
    int t = threadIdx.x;
    int row0 = blockIdx.x * GR;
    int warp = t >> 5, lane = t & 31;

    // load W into smem
    for (int idx = t * 4; idx < F * F; idx += 512 * 4)
        *(float4*)&sW[idx] = *(const float4*)&W[idx];

    // gather: each warp aggregates 4 nodes directly into smem
    const float4* x4 = (const float4*)x;
#pragma unroll
    for (int i = 0; i < 4; i++) {
        int lr = warp * 4 + i;
        int node = row0 + lr;
        float4 a0 = {0.f, 0.f, 0.f, 0.f};
        float4 a1 = {0.f, 0.f, 0.f, 0.f};
        if (node < N_NODES) {
            int beg = g_row_ptr[node], end = g_row_ptr[node + 1];
            int e = beg;
            for (; e + 1 < end; e += 2) {
                int s0 = g_col_idx[e], s1 = g_col_idx[e + 1];
                float4 v0 = x4[s0 * 32 + lane];
                float4 v1 = x4[s1 * 32 + lane];
                if (SRC_NORM) {
                    float w0 = g_out_norm[s0], w1 = g_out_norm[s1];
                    a0.x += w0 * v0.x; a0.y += w0 * v0.y; a0.z += w0 * v0.z; a0.w += w0 * v0.w;
                    a1.x += w1 * v1.x; a1.y += w1 * v1.y; a1.z += w1 * v1.z; a1.w += w1 * v1.w;
                } else {
                    a0.x += v0.x; a0.y += v0.y; a0.z += v0.z; a0.w += v0.w;
                    a1.x += v1.x; a1.y += v1.y; a1.z += v1.z; a1.w += v1.w;
                }
            }
            if (e < end) {
                int s0 = g_col_idx[e];
                float4 v0 = x4[s0 * 32 + lane];
                if (SRC_NORM) {
                    float w0 = g_out_norm[s0];
                    a0.x += w0 * v0.x; a0.y += w0 * v0.y; a0.z += w0 * v0.z; a0.w += w0 * v0.w;
                } else {
                    a0.x += v0.x; a0.y += v0.y; a0.z += v0.z; a0.w += v0.w;
                }
            }
            float sc = g_in_norm[node];
            a0.x = (a0.x + a1.x) * sc;
            a0.y = (a0.y + a1.y) * sc;
            a0.z = (a0.z + a1.z) * sc;
            a0.w = (a0.w + a1.w) * sc;
        }
        *(float4*)&sM[lr * F + lane * 4] = a0;
    }
    __syncthreads();

    // GEMM: thread computes 4x4 tile (rows ty*4.., cols tx*4..)
    int tx = t & 31;
    int ty = t >> 5;   // 0..15
    float acc[4][4];
#pragma unroll
    for (int r = 0; r < 4; r++)
#pragma unroll
        for (int c = 0; c < 4; c++) acc[r][c] = 0.f;

#pragma unroll 8
    for (int k = 0; k < F; k++) {
        float4 w4 = *(float4*)&sW[k * F + tx * 4];
#pragma unroll
        for (int r = 0; r < 4; r++) {
            float mv = sM[(ty * 4 + r) * F + k];
            acc[r][0] += mv * w4.x;
            acc[r][1] += mv * w4.y;
            acc[r][2] += mv * w4.z;
            acc[r][3] += mv * w4.w;
        }
    }

    float4 b4 = *(const float4*)&b[tx * 4];
#pragma unroll
    for (int r = 0; r < 4; r++) {
        int grow = row0 + ty * 4 + r;
        if (grow < N_NODES) {
            float on = g_out_norm[grow];   // prescale for next layer's gather
            float4 o;
            o.x = fmaxf(acc[r][0] + b4.x, 0.f) * on;
            o.y = fmaxf(acc[r][1] + b4.y, 0.f) * on;
            o.z = fmaxf(acc[r][2] + b4.z, 0.f) * on;
            o.w = fmaxf(acc[r][3] + b4.w, 0.f) * on;
            *(float4*)&y[grow * F + tx * 4] = o;
        }
    }
}

// layer-3 aggregation folded into a single 128-vector (input already prescaled
// by out_norm): g_vec = (1/N) * sum_i in_norm[i] * sum_{e: dst=i} x[src]
__global__ void k_agg3(const float* __restrict__ x) {
    __shared__ float sacc[F];
    int t = threadIdx.x;
    if (t < F) sacc[t] = 0.f;
    __syncthreads();
    int w = (blockIdx.x * blockDim.x + t) >> 5;
    int lane = t & 31;
    if (w < N_NODES) {
        int beg = g_row_ptr[w], end = g_row_ptr[w + 1];
        const float4* x4 = (const float4*)x;
        float4 a0 = {0.f, 0.f, 0.f, 0.f};
        float4 a1 = {0.f, 0.f, 0.f, 0.f};
        int e = beg;
        for (; e + 1 < end; e += 2) {
            int s0 = g_col_idx[e], s1 = g_col_idx[e + 1];
            float4 v0 = x4[s0 * 32 + lane];
            float4 v1 = x4[s1 * 32 + lane];
            a0.x += v0.x; a0.y += v0.y; a0.z += v0.z; a0.w += v0.w;
            a1.x += v1.x; a1.y += v1.y; a1.z += v1.z; a1.w += v1.w;
        }
        if (e < end) {
            int s0 = g_col_idx[e];
            float4 v0 = x4[s0 * 32 + lane];
            a0.x += v0.x; a0.y += v0.y; a0.z += v0.z; a0.w += v0.w;
        }
        float sc = g_in_norm[w] * (1.0f / N_NODES);
        atomicAdd(&sacc[lane * 4 + 0], (a0.x + a1.x) * sc);
        atomicAdd(&sacc[lane * 4 + 1], (a0.y + a1.y) * sc);
        atomicAdd(&sacc[lane * 4 + 2], (a0.z + a1.z) * sc);
        atomicAdd(&sacc[lane * 4 + 3], (a0.w + a1.w) * sc);
    }
    __syncthreads();
    if (t < F) atomicAdd(&g_vec[t], sacc[t]);
}

// final 128x128 matvec: out = g_vec @ W3 + b3
__global__ void k_final(const float* __restrict__ W3, const float* __restrict__ b3,
                        float* __restrict__ out) {
    __shared__ float sv[F];
    int j = threadIdx.x;
    sv[j] = g_vec[j];
    __syncthreads();
    float acc = b3[j];
#pragma unroll 8
    for (int k = 0; k < F; k++) acc += sv[k] * W3[k * F + j];
    out[j] = acc;
}

extern "C" void kernel_launch(void* const* d_in, const int* in_sizes, int n_in,
                              void* d_out, int out_size) {
    const float* feat = (const float*)d_in[0];
    const float* W1   = (const float*)d_in[1];
    const float* b1   = (const float*)d_in[2];
    const float* W2   = (const float*)d_in[3];
    const float* b2   = (const float*)d_in[4];
    const float* W3   = (const float*)d_in[5];
    const float* b3   = (const float*)d_in[6];
    const int*   src  = (const int*)d_in[7];
    const int*   dst  = (const int*)d_in[8];
    float* out = (float*)d_out;

    size_t smem_fused = (size_t)(F * F + GR * F) * sizeof(float);   // 96KB
    cudaFuncSetAttribute(k_fused<true>,  cudaFuncAttributeMaxDynamicSharedMemorySize, (int)smem_fused);
    cudaFuncSetAttribute(k_fused<false>, cudaFuncAttributeMaxDynamicSharedMemorySize, (int)smem_fused);

    void *ph1, *ph2;
    cudaGetSymbolAddress(&ph1, g_h1);
    cudaGetSymbolAddress(&ph2, g_h2);
    float* h1 = (float*)ph1;
    float* h2 = (float*)ph2;

    int nb_nodes = (N_NODES + 255) / 256;
    int nb_edges = (N_EDGES + 255) / 256;
    int nb_agg   = (N_NODES * 32 + 255) / 256;        // warp per node
    int nb_fused = (N_NODES + GR - 1) / GR;           // 782

    // graph setup: degrees -> CSR by dst -> norms
    k_init<<<nb_nodes, 256>>>();
    k_count<<<nb_edges, 256>>>(src, dst);
    k_scan1<<<NCH, CH>>>();
    k_scan2<<<1, CH>>>();
    k_scan3<<<nb_nodes, 256>>>();
    k_fill<<<nb_edges, 256>>>(src, dst);

    // layer 1: gather(feat, per-edge out_norm) -> gemm -> relu -> *out_norm
    k_fused<true><<<nb_fused, 512, smem_fused>>>(feat, W1, b1, h1);
    // layer 2: gather(h1) -> gemm -> relu -> *out_norm
    k_fused<false><<<nb_fused, 512, smem_fused>>>(h1, W2, b2, h2);
    // layer 3: gemm folded into mean: vec = mean(in_norm * segsum(h2)); out = vec@W3 + b3
    k_agg3<<<nb_agg, 256>>>(h2);
    k_final<<<1, F>>>(W3, b3, out);
}